// round 13
// baseline (speedup 1.0000x reference)
#include <cuda_runtime.h>
#include <cuda_fp16.h>
#include <math.h>

#define NH 12
#define NB 4
#define SEQ 1024
#define CH 768
#define HD 64
#define BHD 48   // NB*NH
#define QKVLD 2304
#define LOG2E 1.4426950408889634f

// -------- scratch (no allocs allowed) --------
__device__ float g_qkv[NB * SEQ * 3 * CH];     // f32 qkv (Q region only, for relpos)
__device__ __half g_qkvh[NB * SEQ * 3 * CH];   // fp16 qkv (attention)
__device__ __half g_attnh[NB * SEQ * CH];      // fp16 attention output
__device__ __half g_xh[NB * SEQ * CH];         // fp16 x
__device__ __half g_wqkvh[CH * 3 * CH];        // fp16 Wqkv
__device__ __half g_wprojh[CH * CH];           // fp16 Wproj
__device__ float g_relh[BHD * SEQ * 32];
__device__ float g_relw[BHD * SEQ * 32];

__device__ __forceinline__ unsigned su32(const void* p) {
    unsigned a;
    asm("{ .reg .u64 t; cvta.to.shared.u64 t, %1; cvt.u32.u64 %0, t; }" : "=r"(a) : "l"(p));
    return a;
}
__device__ __forceinline__ unsigned f2h2(float lo, float hi) {
    unsigned r;
    asm("cvt.rn.f16x2.f32 %0, %1, %2;" : "=r"(r) : "f"(hi), "f"(lo));
    return r;
}
__device__ __forceinline__ float ex2(float x) {
    float y; asm("ex2.approx.ftz.f32 %0, %1;" : "=f"(y) : "f"(x)); return y;
}
__device__ __forceinline__ void ldm4(unsigned* r, unsigned a) {
    asm volatile("ldmatrix.sync.aligned.m8n8.x4.shared.b16 {%0,%1,%2,%3}, [%4];"
        : "=r"(r[0]), "=r"(r[1]), "=r"(r[2]), "=r"(r[3]) : "r"(a));
}
__device__ __forceinline__ void ldm4t(unsigned* r, unsigned a) {
    asm volatile("ldmatrix.sync.aligned.m8n8.x4.trans.shared.b16 {%0,%1,%2,%3}, [%4];"
        : "=r"(r[0]), "=r"(r[1]), "=r"(r[2]), "=r"(r[3]) : "r"(a));
}
__device__ __forceinline__ void mma_f16(float* d, const unsigned* a, const unsigned* b) {
    asm volatile(
        "mma.sync.aligned.m16n8k16.row.col.f32.f16.f16.f32 "
        "{%0,%1,%2,%3}, {%4,%5,%6,%7}, {%8,%9}, {%0,%1,%2,%3};\n"
        : "+f"(d[0]), "+f"(d[1]), "+f"(d[2]), "+f"(d[3])
        : "r"(a[0]), "r"(a[1]), "r"(a[2]), "r"(a[3]), "r"(b[0]), "r"(b[1]));
}
__device__ __forceinline__ void cpa16(unsigned dst, const void* src) {
    asm volatile("cp.async.cg.shared.global [%0], [%1], 16;\n" :: "r"(dst), "l"(src));
}
#define CP_COMMIT() asm volatile("cp.async.commit_group;\n")
#define CP_WAIT1() asm volatile("cp.async.wait_group 1;\n")
#define CP_WAIT0() asm volatile("cp.async.wait_group 0;\n")

// ============================================================
// f32 -> f16 conversion (pairs)
// ============================================================
__global__ void f2h_kernel(const float* __restrict__ s, __half* __restrict__ d, int n2) {
    int i = blockIdx.x * 256 + threadIdx.x;
    if (i < n2) {
        float2 v = ((const float2*)s)[i];
        ((unsigned*)d)[i] = f2h2(v.x, v.y);
    }
}

// ============================================================
// FP16 GEMM, cp.async 3-stage pipeline, BK=64.
// C[M,N] = A[M,K]@B[K,N]. Block 128x128, 256 thr, 8 warps (2m x 4n).
// A smem rows 144B (9 granules mod 8 = bijective -> conflict-free ldmatrix),
// B smem rows 272B (17 mod 8 = 1). 12 k-chunks of 64.
// MODE 1: f32 out + bias (out-proj). MODE 2: f16 out + f32 iff bn<768 (QKV).
// ============================================================
#define G_ASTAGE (128 * 144)
#define G_BSTAGE (64 * 272)
#define GEMM_SMEM (3 * (G_ASTAGE + G_BSTAGE))

template <int MODE>
__global__ __launch_bounds__(256) void gemm_h(
    const __half* __restrict__ A, const __half* __restrict__ B,
    const float* __restrict__ bias, float* __restrict__ Cf, __half* __restrict__ Ch,
    int M, int N, int K) {
    extern __shared__ __align__(16) char gsm[];
    const unsigned sb = su32(gsm);

    int tid = threadIdx.x;
    int lane = tid & 31, w = tid >> 5;
    int g = lane >> 2, t4 = lane & 3;
    int wm = (w & 1) * 64, wn = (w >> 1) * 32;
    int bm = blockIdx.y * 128, bn = blockIdx.x * 128;

    // cp.async mappings (BK=64)
    const int a_row = tid >> 1, a_h = (tid & 1) * 32;   // 4 granules from half a_h
    const int b_row = tid >> 2, b_h = (tid & 3) * 32;   // 4 granules from half b_h
    const __half* aSrc = A + (size_t)(bm + a_row) * K + a_h;
    const __half* bSrc = B + (size_t)b_row * N + bn + b_h;

    // ldmatrix lane geometry
    const int rl = (lane & 7) + 8 * ((lane >> 3) & 1);
    const int gl = lane >> 4;

    float acc[4][4][4];
#pragma unroll
    for (int i = 0; i < 4; i++)
#pragma unroll
        for (int j = 0; j < 4; j++)
#pragma unroll
            for (int r = 0; r < 4; r++) acc[i][j][r] = 0.f;

    auto issue = [&](int kc) {
        int s = kc % 3, k0 = kc * 64;
        unsigned ad = sb + s * G_ASTAGE + a_row * 144 + a_h * 2;
        const __half* ap = aSrc + k0;
#pragma unroll
        for (int q = 0; q < 4; q++) cpa16(ad + 16 * q, ap + 8 * q);
        unsigned bd = sb + 3 * G_ASTAGE + s * G_BSTAGE + b_row * 272 + b_h * 2;
        const __half* bp = bSrc + (size_t)k0 * N;
#pragma unroll
        for (int q = 0; q < 4; q++) cpa16(bd + 16 * q, bp + 8 * q);
    };

    issue(0); CP_COMMIT();
    issue(1); CP_COMMIT();

    const int KC = K >> 6;
    for (int kc = 0; kc < KC; kc++) {
        CP_WAIT1();
        __syncthreads();
        if (kc + 2 < KC) issue(kc + 2);
        CP_COMMIT();

        int s = kc % 3;
        unsigned aB = sb + s * G_ASTAGE;
        unsigned bB = sb + 3 * G_ASTAGE + s * G_BSTAGE;
#pragma unroll
        for (int c = 0; c < 4; c++) {
            unsigned af[4][4], bf[4][2];
#pragma unroll
            for (int i = 0; i < 4; i++)
                ldm4(af[i], aB + (wm + 16 * i + rl) * 144 + (2 * c + gl) * 16);
#pragma unroll
            for (int jp = 0; jp < 2; jp++) {
                unsigned r[4];
                ldm4t(r, bB + (16 * c + rl) * 272 + ((wn >> 3) + 2 * jp + gl) * 16);
                bf[2 * jp][0] = r[0]; bf[2 * jp][1] = r[1];
                bf[2 * jp + 1][0] = r[2]; bf[2 * jp + 1][1] = r[3];
            }
#pragma unroll
            for (int i = 0; i < 4; i++)
#pragma unroll
                for (int j = 0; j < 4; j++)
                    mma_f16(acc[i][j], af[i], bf[j]);
        }
    }

#pragma unroll
    for (int i = 0; i < 4; i++)
#pragma unroll
        for (int j = 0; j < 4; j++) {
            int row = bm + wm + 16 * i + g;
            int col = bn + wn + 8 * j + 2 * t4;
            float2 v0 = make_float2(acc[i][j][0], acc[i][j][1]);
            float2 v1 = make_float2(acc[i][j][2], acc[i][j][3]);
            if (MODE == 1) {
                float2 bb = *(const float2*)&bias[col];
                v0.x += bb.x; v0.y += bb.y; v1.x += bb.x; v1.y += bb.y;
                *(float2*)&Cf[(size_t)row * N + col] = v0;
                *(float2*)&Cf[(size_t)(row + 8) * N + col] = v1;
            } else {
                *(unsigned*)&Ch[(size_t)row * N + col] = f2h2(v0.x, v0.y);
                *(unsigned*)&Ch[(size_t)(row + 8) * N + col] = f2h2(v1.x, v1.y);
                if (bn < CH) {   // Q region also in f32 for relpos
                    *(float2*)&Cf[(size_t)row * N + col] = v0;
                    *(float2*)&Cf[(size_t)(row + 8) * N + col] = v1;
                }
            }
        }
}

// ============================================================
// Relative position bias (unchanged; reads f32 Q region of g_qkv).
// ============================================================
__global__ __launch_bounds__(256) void relpos_kernel(
    const float* __restrict__ rph, const float* __restrict__ rpw) {
    __shared__ float Rh[63 * 68], Rw[63 * 68];
    int tid = threadIdx.x;
    int qc = blockIdx.x, bh = blockIdx.y;

    for (int idx = tid; idx < 63 * 64; idx += 256) {
        int row = idx >> 6, d = idx & 63;
        Rh[row * 68 + d] = rph[idx];
        Rw[row * 68 + d] = rpw[idx];
    }
    __syncthreads();

    int ql = tid >> 1, half = tid & 1;
    int q = qc * 128 + ql;
    int b = bh / NH, head = bh % NH;
    int pc = half ? (q & 31) : (q >> 5);
    const float* qptr = &g_qkv[(size_t)(b * SEQ + q) * QKVLD + head * HD];
    const float* T = half ? Rw : Rh;

    float acc[32];
#pragma unroll
    for (int o = 0; o < 32; o++) acc[o] = 0.f;

    for (int d0 = 0; d0 < 64; d0 += 8) {
        float4 v0 = *(const float4*)&qptr[d0];
        float4 v1 = *(const float4*)&qptr[d0 + 4];
        float qd[8] = {v0.x, v0.y, v0.z, v0.w, v1.x, v1.y, v1.z, v1.w};
#pragma unroll
        for (int dd = 0; dd < 8; dd++) {
            float qv = qd[dd];
            const float* Tp = &T[(pc + 31) * 68 + d0 + dd];
#pragma unroll
            for (int o = 0; o < 32; o++)
                acc[o] = fmaf(qv, Tp[-o * 68], acc[o]);
        }
    }
    float* dst = half ? &g_relw[((size_t)bh * SEQ + q) * 32]
                      : &g_relh[((size_t)bh * SEQ + q) * 32];
#pragma unroll
    for (int o = 0; o < 32; o++) dst[o] = acc[o];
}

// ============================================================
// Flash attention: fp16 MMA, P kept entirely in registers
// (QK^T C-frag layout == PV A-frag layout for m16n8k16).
// Bq=128, Bk=64, 256 thr, 8 warps; warp owns 16 q-rows x 64 kv cols.
// cp.async double-buffered K/V, ONE __syncthreads per iteration.
// ============================================================
#define BQ 128
#define LDH 33
#define KV_STG 9216                    // bytes per K (or V) stage
#define AT_BOFF (4 * KV_STG)
#define ATTN_SMEM (AT_BOFF + BQ * LDH * 4)

__global__ __launch_bounds__(256, 2) void attn_mma() {
    extern __shared__ __align__(16) char sm[];
    const unsigned sb = su32(sm);
    float* Bhs = (float*)(sm + AT_BOFF);

    int tid = threadIdx.x;
    int lane = tid & 31, w = tid >> 5;
    int g = lane >> 2, t4 = lane & 3;

    int bh = blockIdx.y, qbase = blockIdx.x * BQ;
    int b = bh / NH, head = bh % NH;
    const __half* baseh = g_qkvh + (size_t)b * SEQ * QKVLD + head * HD;

    // stage relh (log2 domain)
    {
        const float* gh = &g_relh[((size_t)bh * SEQ + qbase) * 32];
        for (int idx = tid; idx < BQ * 32; idx += 256) {
            int r = idx >> 5, c = idx & 31;
            Bhs[r * LDH + c] = LOG2E * gh[r * 32 + c];
        }
    }

    int qr0 = w * 16 + g;
    int qr1 = qr0 + 8;

    // Q fragments: direct fp16 loads
    unsigned qa[4][4];
    {
        const __half* qp0 = baseh + (size_t)(qbase + qr0) * QKVLD;
        const __half* qp1 = baseh + (size_t)(qbase + qr1) * QKVLD;
#pragma unroll
        for (int c = 0; c < 4; c++) {
            qa[c][0] = *(const unsigned*)&qp0[16 * c + 2 * t4];
            qa[c][1] = *(const unsigned*)&qp1[16 * c + 2 * t4];
            qa[c][2] = *(const unsigned*)&qp0[16 * c + 2 * t4 + 8];
            qa[c][3] = *(const unsigned*)&qp1[16 * c + 2 * t4 + 8];
        }
    }
    // relw registers, log2 domain
    float rw0[8], rw1[8];
    {
        const float* p0 = &g_relw[((size_t)bh * SEQ + qbase + qr0) * 32];
        const float* p1 = &g_relw[((size_t)bh * SEQ + qbase + qr1) * 32];
#pragma unroll
        for (int m = 0; m < 4; m++) {
            rw0[2 * m]     = LOG2E * p0[8 * m + 2 * t4];
            rw0[2 * m + 1] = LOG2E * p0[8 * m + 2 * t4 + 1];
            rw1[2 * m]     = LOG2E * p1[8 * m + 2 * t4];
            rw1[2 * m + 1] = LOG2E * p1[8 * m + 2 * t4 + 1];
        }
    }

    float m0 = -1e30f, m1 = -1e30f, l0 = 0.f, l1 = 0.f;
    float oacc[8][4];
#pragma unroll
    for (int nb = 0; nb < 8; nb++)
#pragma unroll
        for (int r = 0; r < 4; r++) oacc[nb][r] = 0.f;

    // cp.async K/V mapping
    const int kv_r = tid >> 2, kv_g = (tid & 3) * 2;
    const __half* kvSrc = baseh + (size_t)kv_r * QKVLD + CH + 8 * kv_g;

    auto issue = [&](int kt) {
        int s = kt & 1;
        const __half* kp = kvSrc + (size_t)(kt * 64) * QKVLD;
        unsigned kd = sb + s * KV_STG + kv_r * 144 + kv_g * 16;
        cpa16(kd, kp);
        cpa16(kd + 16, kp + 8);
        const __half* vp = kp + CH;
        unsigned vd = kd + 2 * KV_STG;
        cpa16(vd, vp);
        cpa16(vd + 16, vp + 8);
    };

    const float sc = 0.125f * LOG2E;

    // ldmatrix lane geometry
    const int l7 = lane & 7, le = (lane >> 3) & 1, lh = lane >> 4;
    const int krow_l = 8 * lh + l7;
    const int vrow_l = l7 + 8 * le;

    issue(0); CP_COMMIT();

    for (int kt = 0; kt < 16; kt++) {
        CP_WAIT0();
        __syncthreads();   // buffer kt visible; all warps done reading buffer kt-1
        if (kt + 1 < 16) issue(kt + 1);
        CP_COMMIT();

        const unsigned kB = sb + (kt & 1) * KV_STG;
        const unsigned vB = kB + 2 * KV_STG;

        // S = Q K^T
        float sacc[8][4];
#pragma unroll
        for (int nb = 0; nb < 8; nb++)
#pragma unroll
            for (int r = 0; r < 4; r++) sacc[nb][r] = 0.f;
#pragma unroll
        for (int c = 0; c < 4; c++) {
#pragma unroll
            for (int nbp = 0; nbp < 4; nbp++) {
                unsigned kb[4];
                ldm4(kb, kB + (16 * nbp + krow_l) * 144 + c * 32 + le * 16);
                mma_f16(sacc[2 * nbp], qa[c], kb);
                mma_f16(sacc[2 * nbp + 1], qa[c], kb + 2);
            }
        }

        // bias + warp-local online softmax (log2 domain)
        float rh0a = Bhs[qr0 * LDH + 2 * kt], rh0b = Bhs[qr0 * LDH + 2 * kt + 1];
        float rh1a = Bhs[qr1 * LDH + 2 * kt], rh1b = Bhs[qr1 * LDH + 2 * kt + 1];
        float mn0 = m0, mn1 = m1;
#pragma unroll
        for (int nb = 0; nb < 8; nb++) {
            float bh0 = nb < 4 ? rh0a : rh0b;
            float bh1 = nb < 4 ? rh1a : rh1b;
            int mi = nb & 3;
            sacc[nb][0] = fmaf(sc, sacc[nb][0], bh0 + rw0[2 * mi]);
            sacc[nb][1] = fmaf(sc, sacc[nb][1], bh0 + rw0[2 * mi + 1]);
            sacc[nb][2] = fmaf(sc, sacc[nb][2], bh1 + rw1[2 * mi]);
            sacc[nb][3] = fmaf(sc, sacc[nb][3], bh1 + rw1[2 * mi + 1]);
            mn0 = fmaxf(mn0, fmaxf(sacc[nb][0], sacc[nb][1]));
            mn1 = fmaxf(mn1, fmaxf(sacc[nb][2], sacc[nb][3]));
        }
        mn0 = fmaxf(mn0, __shfl_xor_sync(0xffffffffu, mn0, 1));
        mn0 = fmaxf(mn0, __shfl_xor_sync(0xffffffffu, mn0, 2));
        mn1 = fmaxf(mn1, __shfl_xor_sync(0xffffffffu, mn1, 1));
        mn1 = fmaxf(mn1, __shfl_xor_sync(0xffffffffu, mn1, 2));
        float cr0 = ex2(m0 - mn0), cr1 = ex2(m1 - mn1);
        m0 = mn0; m1 = mn1;
        float s0 = 0.f, s1 = 0.f;
        unsigned ph[8][2];   // P directly in A-fragment layout
#pragma unroll
        for (int nb = 0; nb < 8; nb++) {
            float p0 = ex2(sacc[nb][0] - mn0);
            float p1 = ex2(sacc[nb][1] - mn0);
            float p2 = ex2(sacc[nb][2] - mn1);
            float p3 = ex2(sacc[nb][3] - mn1);
            s0 += p0 + p1; s1 += p2 + p3;
            ph[nb][0] = f2h2(p0, p1);
            ph[nb][1] = f2h2(p2, p3);
        }
        s0 += __shfl_xor_sync(0xffffffffu, s0, 1);
        s0 += __shfl_xor_sync(0xffffffffu, s0, 2);
        s1 += __shfl_xor_sync(0xffffffffu, s1, 1);
        s1 += __shfl_xor_sync(0xffffffffu, s1, 2);
        l0 = l0 * cr0 + s0;
        l1 = l1 * cr1 + s1;
#pragma unroll
        for (int nb = 0; nb < 8; nb++) {
            oacc[nb][0] *= cr0; oacc[nb][1] *= cr0;
            oacc[nb][2] *= cr1; oacc[nb][3] *= cr1;
        }

        // O += P @ V  (P a-frags straight from registers)
#pragma unroll
        for (int c = 0; c < 4; c++) {
            unsigned pa[4] = {ph[2 * c][0], ph[2 * c][1], ph[2 * c + 1][0], ph[2 * c + 1][1]};
#pragma unroll
            for (int nbp = 0; nbp < 4; nbp++) {
                unsigned vb[4];
                ldm4t(vb, vB + (16 * c + vrow_l) * 144 + nbp * 32 + lh * 16);
                mma_f16(oacc[2 * nbp], pa, vb);
                mma_f16(oacc[2 * nbp + 1], pa, vb + 2);
            }
        }
    }

    // normalize + write fp16 (B,S,C) layout
    float inv0 = 1.f / l0, inv1 = 1.f / l1;
    __half* op0 = &g_attnh[(size_t)(b * SEQ + qbase + qr0) * CH + head * HD + 2 * t4];
    __half* op1 = &g_attnh[(size_t)(b * SEQ + qbase + qr1) * CH + head * HD + 2 * t4];
#pragma unroll
    for (int nb = 0; nb < 8; nb++) {
        *(unsigned*)&op0[8 * nb] = f2h2(oacc[nb][0] * inv0, oacc[nb][1] * inv0);
        *(unsigned*)&op1[8 * nb] = f2h2(oacc[nb][2] * inv1, oacc[nb][3] * inv1);
    }
}

// ============================================================
extern "C" void kernel_launch(void* const* d_in, const int* in_sizes, int n_in,
                              void* d_out, int out_size) {
    const float* x     = (const float*)d_in[0];
    const float* Wqkv  = (const float*)d_in[1];
    const float* Wproj = (const float*)d_in[2];
    const float* bproj = (const float*)d_in[3];
    const float* rph   = (const float*)d_in[4];
    const float* rpw   = (const float*)d_in[5];
    float* out = (float*)d_out;

    float* qkv;   cudaGetSymbolAddress((void**)&qkv,   g_qkv);
    __half* qkvh; cudaGetSymbolAddress((void**)&qkvh,  g_qkvh);
    __half* attnh; cudaGetSymbolAddress((void**)&attnh, g_attnh);
    __half* xh;   cudaGetSymbolAddress((void**)&xh,    g_xh);
    __half* wqh;  cudaGetSymbolAddress((void**)&wqh,   g_wqkvh);
    __half* wph;  cudaGetSymbolAddress((void**)&wph,   g_wprojh);

    cudaFuncSetAttribute(gemm_h<1>, cudaFuncAttributeMaxDynamicSharedMemorySize, GEMM_SMEM);
    cudaFuncSetAttribute(gemm_h<2>, cudaFuncAttributeMaxDynamicSharedMemorySize, GEMM_SMEM);
    cudaFuncSetAttribute(attn_mma, cudaFuncAttributeMaxDynamicSharedMemorySize, ATTN_SMEM);

    // 0) f32 -> f16 conversions
    {
        int n2 = NB * SEQ * CH / 2;
        f2h_kernel<<<(n2 + 255) / 256, 256>>>(x, xh, n2);
        n2 = CH * 3 * CH / 2;
        f2h_kernel<<<(n2 + 255) / 256, 256>>>(Wqkv, wqh, n2);
        n2 = CH * CH / 2;
        f2h_kernel<<<(n2 + 255) / 256, 256>>>(Wproj, wph, n2);
    }

    // 1) QKV projection: fp16 out (+ f32 Q region for relpos)
    gemm_h<2><<<dim3(QKVLD / 128, (NB * SEQ) / 128), 256, GEMM_SMEM>>>(
        xh, wqh, nullptr, qkv, qkvh, NB * SEQ, QKVLD, CH);

    // 2) decomposed relative position bias
    relpos_kernel<<<dim3(8, BHD), 256>>>(rph, rpw);

    // 3) attention (fp16 mma, register-resident P, single-sync loop)
    attn_mma<<<dim3(SEQ / BQ, BHD), 256, ATTN_SMEM>>>();

    // 4) out projection + bias -> f32 output
    gemm_h<1><<<dim3(CH / 128, (NB * SEQ) / 128), 256, GEMM_SMEM>>>(
        attnh, wph, bproj, out, nullptr, NB * SEQ, CH, CH);
}

// round 17
// speedup vs baseline: 1.4340x; 1.4340x over previous
#include <cuda_runtime.h>
#include <cuda_fp16.h>
#include <math.h>

#define NH 12
#define NB 4
#define SEQ 1024
#define CH 768
#define HD 64
#define BHD 48   // NB*NH
#define QKVLD 2304
#define LOG2E 1.4426950408889634f

// -------- scratch (no allocs allowed) --------
__device__ __half g_qkvh[NB * SEQ * 3 * CH];   // fp16 qkv
__device__ __half g_attnh[NB * SEQ * CH];      // fp16 attention output
__device__ __half g_xh[NB * SEQ * CH];         // fp16 x
__device__ __half g_wqkvh[CH * 3 * CH];        // fp16 Wqkv
__device__ __half g_wprojh[CH * CH];           // fp16 Wproj
__device__ float g_relh[BHD * SEQ * 32];
__device__ float g_relw[BHD * SEQ * 32];

__device__ __forceinline__ unsigned su32(const void* p) {
    unsigned a;
    asm("{ .reg .u64 t; cvta.to.shared.u64 t, %1; cvt.u32.u64 %0, t; }" : "=r"(a) : "l"(p));
    return a;
}
__device__ __forceinline__ unsigned f2h2(float lo, float hi) {
    unsigned r;
    asm("cvt.rn.f16x2.f32 %0, %1, %2;" : "=r"(r) : "f"(hi), "f"(lo));
    return r;
}
__device__ __forceinline__ float ex2(float x) {
    float y; asm("ex2.approx.ftz.f32 %0, %1;" : "=f"(y) : "f"(x)); return y;
}
__device__ __forceinline__ void ldm4(unsigned* r, unsigned a) {
    asm volatile("ldmatrix.sync.aligned.m8n8.x4.shared.b16 {%0,%1,%2,%3}, [%4];"
        : "=r"(r[0]), "=r"(r[1]), "=r"(r[2]), "=r"(r[3]) : "r"(a));
}
__device__ __forceinline__ void ldm4t(unsigned* r, unsigned a) {
    asm volatile("ldmatrix.sync.aligned.m8n8.x4.trans.shared.b16 {%0,%1,%2,%3}, [%4];"
        : "=r"(r[0]), "=r"(r[1]), "=r"(r[2]), "=r"(r[3]) : "r"(a));
}
__device__ __forceinline__ void mma_f16(float* d, const unsigned* a, const unsigned* b) {
    asm volatile(
        "mma.sync.aligned.m16n8k16.row.col.f32.f16.f16.f32 "
        "{%0,%1,%2,%3}, {%4,%5,%6,%7}, {%8,%9}, {%0,%1,%2,%3};\n"
        : "+f"(d[0]), "+f"(d[1]), "+f"(d[2]), "+f"(d[3])
        : "r"(a[0]), "r"(a[1]), "r"(a[2]), "r"(a[3]), "r"(b[0]), "r"(b[1]));
}
__device__ __forceinline__ void cpa16(unsigned dst, const void* src) {
    asm volatile("cp.async.cg.shared.global [%0], [%1], 16;\n" :: "r"(dst), "l"(src));
}
#define CP_COMMIT() asm volatile("cp.async.commit_group;\n")
#define CP_WAIT1() asm volatile("cp.async.wait_group 1;\n")
#define CP_WAIT0() asm volatile("cp.async.wait_group 0;\n")

// ============================================================
// f32 -> f16 conversion (pairs)
// ============================================================
__global__ void f2h_kernel(const float* __restrict__ s, __half* __restrict__ d, int n2) {
    int i = blockIdx.x * 256 + threadIdx.x;
    if (i < n2) {
        float2 v = ((const float2*)s)[i];
        ((unsigned*)d)[i] = f2h2(v.x, v.y);
    }
}

// ============================================================
// FP16 GEMM, cp.async 3-stage pipeline, BK=32  (R12-proven).
// Block 128x128, 256 thr, 8 warps (2m x 4n).
// A smem rows 80B, B smem rows 272B: conflict-free ldmatrix, no swizzle.
// MODE 1: f32 out + bias (out-proj). MODE 2: f16 out (QKV).
// ============================================================
#define G_ASTAGE 10240
#define G_BSTAGE 8704
#define GEMM_SMEM (3 * (G_ASTAGE + G_BSTAGE))

template <int MODE>
__global__ __launch_bounds__(256) void gemm_h(
    const __half* __restrict__ A, const __half* __restrict__ B,
    const float* __restrict__ bias, float* __restrict__ Cf, __half* __restrict__ Ch,
    int M, int N, int K) {
    extern __shared__ __align__(16) char gsm[];
    const unsigned sb = su32(gsm);

    int tid = threadIdx.x;
    int lane = tid & 31, w = tid >> 5;
    int g = lane >> 2, t4 = lane & 3;
    int wm = (w & 1) * 64, wn = (w >> 1) * 32;
    int bm = blockIdx.y * 128, bn = blockIdx.x * 128;

    const int a_row = tid >> 1, a_g = (tid & 1) * 2;
    const int b_row = tid >> 4, b_g = tid & 15;
    const __half* aSrc = A + (size_t)(bm + a_row) * K + 8 * a_g;
    const __half* bSrc = B + (size_t)b_row * N + bn + 8 * b_g;

    const int rl = (lane & 7) + 8 * ((lane >> 3) & 1);
    const int gl = lane >> 4;

    float acc[4][4][4];
#pragma unroll
    for (int i = 0; i < 4; i++)
#pragma unroll
        for (int j = 0; j < 4; j++)
#pragma unroll
            for (int r = 0; r < 4; r++) acc[i][j][r] = 0.f;

    auto issue = [&](int kc) {
        int s = kc % 3, k0 = kc * 32;
        unsigned ad = sb + s * G_ASTAGE + a_row * 80 + a_g * 16;
        const __half* ap = aSrc + k0;
        cpa16(ad, ap);
        cpa16(ad + 16, ap + 8);
        unsigned bd = sb + 3 * G_ASTAGE + s * G_BSTAGE + b_row * 272 + b_g * 16;
        const __half* bp = bSrc + (size_t)k0 * N;
        cpa16(bd, bp);
        cpa16(bd + 16 * 272, bp + (size_t)16 * N);
    };

    issue(0); CP_COMMIT();
    issue(1); CP_COMMIT();

    const int KC = K >> 5;
    for (int kc = 0; kc < KC; kc++) {
        CP_WAIT1();
        __syncthreads();
        if (kc + 2 < KC) issue(kc + 2);
        CP_COMMIT();

        int s = kc % 3;
        unsigned aB = sb + s * G_ASTAGE;
        unsigned bB = sb + 3 * G_ASTAGE + s * G_BSTAGE;
#pragma unroll
        for (int c = 0; c < 2; c++) {
            unsigned af[4][4], bf[4][2];
#pragma unroll
            for (int i = 0; i < 4; i++)
                ldm4(af[i], aB + (wm + 16 * i + rl) * 80 + (2 * c + gl) * 16);
#pragma unroll
            for (int jp = 0; jp < 2; jp++) {
                unsigned r[4];
                ldm4t(r, bB + (16 * c + rl) * 272 + ((wn >> 3) + 2 * jp + gl) * 16);
                bf[2 * jp][0] = r[0]; bf[2 * jp][1] = r[1];
                bf[2 * jp + 1][0] = r[2]; bf[2 * jp + 1][1] = r[3];
            }
#pragma unroll
            for (int i = 0; i < 4; i++)
#pragma unroll
                for (int j = 0; j < 4; j++)
                    mma_f16(acc[i][j], af[i], bf[j]);
        }
    }

#pragma unroll
    for (int i = 0; i < 4; i++)
#pragma unroll
        for (int j = 0; j < 4; j++) {
            int row = bm + wm + 16 * i + g;
            int col = bn + wn + 8 * j + 2 * t4;
            float2 v0 = make_float2(acc[i][j][0], acc[i][j][1]);
            float2 v1 = make_float2(acc[i][j][2], acc[i][j][3]);
            if (MODE == 1) {
                float2 bb = *(const float2*)&bias[col];
                v0.x += bb.x; v0.y += bb.y; v1.x += bb.x; v1.y += bb.y;
                *(float2*)&Cf[(size_t)row * N + col] = v0;
                *(float2*)&Cf[(size_t)(row + 8) * N + col] = v1;
            } else {
                *(unsigned*)&Ch[(size_t)row * N + col] = f2h2(v0.x, v0.y);
                *(unsigned*)&Ch[(size_t)(row + 8) * N + col] = f2h2(v1.x, v1.y);
            }
        }
}

// ============================================================
// Tensor-core relpos. Grid (2, BHD): x=0 -> rel_h, x=1 -> rel_w.
// Per block: 8 warps, warp handles 4 group values (qh for rel_h, qw for rel_w).
// For each grp: C(32x32) = Q(32x64) @ T_sel(32x64)^T, where T_sel row for
// output col n is table[grp+31-n] (reversal free via per-lane ldmatrix addrs).
// Table staged fp16 in smem, rows padded to 72 halves (144B, conflict-free).
// ============================================================
__global__ __launch_bounds__(256) void relpos_mma(
    const float* __restrict__ rph, const float* __restrict__ rpw) {
    __shared__ __align__(16) unsigned Tt[63 * 36];   // [63][36] half2
    int tid = threadIdx.x;
    int lane = tid & 31, w = tid >> 5;
    int g = lane >> 2, t4 = lane & 3;
    int half = blockIdx.x, bh = blockIdx.y;
    int b = bh / NH, head = bh % NH;

    const float* src = half ? rpw : rph;
    for (int idx = tid; idx < 63 * 32; idx += 256) {
        int row = idx >> 5, dp = idx & 31;
        Tt[row * 36 + dp] = f2h2(src[row * 64 + 2 * dp], src[row * 64 + 2 * dp + 1]);
    }
    __syncthreads();

    const unsigned tBase = su32(Tt);
    const int l7 = lane & 7, le = (lane >> 3) & 1, lh = lane >> 4;
    const __half* qbase = g_qkvh + (size_t)b * SEQ * QKVLD + head * HD;
    float* dst = (half ? g_relw : g_relh) + (size_t)bh * SEQ * 32;

#pragma unroll
    for (int gi = 0; gi < 4; gi++) {
        int grp = w * 4 + gi;
        // A fragments: rows 16i+g, 16i+8+g of the 32-row Q slab
        unsigned qa[2][4][4];
#pragma unroll
        for (int i = 0; i < 2; i++) {
            int m0 = 16 * i + g, m1 = m0 + 8;
            int q0 = half ? 32 * m0 + grp : 32 * grp + m0;
            int q1 = half ? 32 * m1 + grp : 32 * grp + m1;
            const __half* qp0 = qbase + (size_t)q0 * QKVLD;
            const __half* qp1 = qbase + (size_t)q1 * QKVLD;
#pragma unroll
            for (int c = 0; c < 4; c++) {
                qa[i][c][0] = *(const unsigned*)&qp0[16 * c + 2 * t4];
                qa[i][c][1] = *(const unsigned*)&qp1[16 * c + 2 * t4];
                qa[i][c][2] = *(const unsigned*)&qp0[16 * c + 2 * t4 + 8];
                qa[i][c][3] = *(const unsigned*)&qp1[16 * c + 2 * t4 + 8];
            }
        }
        float sacc[2][4][4];
#pragma unroll
        for (int i = 0; i < 2; i++)
#pragma unroll
            for (int j = 0; j < 4; j++)
#pragma unroll
                for (int r = 0; r < 4; r++) sacc[i][j][r] = 0.f;
#pragma unroll
        for (int c = 0; c < 4; c++) {
#pragma unroll
            for (int nbp = 0; nbp < 2; nbp++) {
                // table row for output col n = grp + 31 - n, n = 16*nbp + 8*lh + l7
                int trow = grp + 31 - (16 * nbp + 8 * lh + l7);
                unsigned kb[4];
                ldm4(kb, tBase + (trow * 36 + c * 8 + le * 4) * 4);
#pragma unroll
                for (int i = 0; i < 2; i++) {
                    mma_f16(sacc[i][2 * nbp], qa[i][c], kb);
                    mma_f16(sacc[i][2 * nbp + 1], qa[i][c], kb + 2);
                }
            }
        }
#pragma unroll
        for (int i = 0; i < 2; i++) {
            int m0 = 16 * i + g, m1 = m0 + 8;
            int q0 = half ? 32 * m0 + grp : 32 * grp + m0;
            int q1 = half ? 32 * m1 + grp : 32 * grp + m1;
#pragma unroll
            for (int j = 0; j < 4; j++) {
                int col = 8 * j + 2 * t4;
                *(float2*)&dst[(size_t)q0 * 32 + col] = make_float2(sacc[i][j][0], sacc[i][j][1]);
                *(float2*)&dst[(size_t)q1 * 32 + col] = make_float2(sacc[i][j][2], sacc[i][j][3]);
            }
        }
    }
}

// ============================================================
// Flash attention: fp16 MMA, register-resident P, one sync/iter (R13).
// Bq=128, Bk=64, 256 thr, 8 warps; warp owns 16 q-rows x 64 kv cols.
// ============================================================
#define BQ 128
#define LDH 33
#define KV_STG 9216
#define AT_BOFF (4 * KV_STG)
#define ATTN_SMEM (AT_BOFF + BQ * LDH * 4)

__global__ __launch_bounds__(256, 2) void attn_mma() {
    extern __shared__ __align__(16) char sm[];
    const unsigned sb = su32(sm);
    float* Bhs = (float*)(sm + AT_BOFF);

    int tid = threadIdx.x;
    int lane = tid & 31, w = tid >> 5;
    int g = lane >> 2, t4 = lane & 3;

    int bh = blockIdx.y, qbase = blockIdx.x * BQ;
    int b = bh / NH, head = bh % NH;
    const __half* baseh = g_qkvh + (size_t)b * SEQ * QKVLD + head * HD;

    {
        const float* gh = &g_relh[((size_t)bh * SEQ + qbase) * 32];
        for (int idx = tid; idx < BQ * 32; idx += 256) {
            int r = idx >> 5, c = idx & 31;
            Bhs[r * LDH + c] = LOG2E * gh[r * 32 + c];
        }
    }

    int qr0 = w * 16 + g;
    int qr1 = qr0 + 8;

    unsigned qa[4][4];
    {
        const __half* qp0 = baseh + (size_t)(qbase + qr0) * QKVLD;
        const __half* qp1 = baseh + (size_t)(qbase + qr1) * QKVLD;
#pragma unroll
        for (int c = 0; c < 4; c++) {
            qa[c][0] = *(const unsigned*)&qp0[16 * c + 2 * t4];
            qa[c][1] = *(const unsigned*)&qp1[16 * c + 2 * t4];
            qa[c][2] = *(const unsigned*)&qp0[16 * c + 2 * t4 + 8];
            qa[c][3] = *(const unsigned*)&qp1[16 * c + 2 * t4 + 8];
        }
    }
    float rw0[8], rw1[8];
    {
        const float* p0 = &g_relw[((size_t)bh * SEQ + qbase + qr0) * 32];
        const float* p1 = &g_relw[((size_t)bh * SEQ + qbase + qr1) * 32];
#pragma unroll
        for (int m = 0; m < 4; m++) {
            rw0[2 * m]     = LOG2E * p0[8 * m + 2 * t4];
            rw0[2 * m + 1] = LOG2E * p0[8 * m + 2 * t4 + 1];
            rw1[2 * m]     = LOG2E * p1[8 * m + 2 * t4];
            rw1[2 * m + 1] = LOG2E * p1[8 * m + 2 * t4 + 1];
        }
    }

    float m0 = -1e30f, m1 = -1e30f, l0 = 0.f, l1 = 0.f;
    float oacc[8][4];
#pragma unroll
    for (int nb = 0; nb < 8; nb++)
#pragma unroll
        for (int r = 0; r < 4; r++) oacc[nb][r] = 0.f;

    const int kv_r = tid >> 2, kv_g = (tid & 3) * 2;
    const __half* kvSrc = baseh + (size_t)kv_r * QKVLD + CH + 8 * kv_g;

    auto issue = [&](int kt) {
        int s = kt & 1;
        const __half* kp = kvSrc + (size_t)(kt * 64) * QKVLD;
        unsigned kd = sb + s * KV_STG + kv_r * 144 + kv_g * 16;
        cpa16(kd, kp);
        cpa16(kd + 16, kp + 8);
        const __half* vp = kp + CH;
        unsigned vd = kd + 2 * KV_STG;
        cpa16(vd, vp);
        cpa16(vd + 16, vp + 8);
    };

    const float sc = 0.125f * LOG2E;
    const int l7 = lane & 7, le = (lane >> 3) & 1, lh = lane >> 4;
    const int krow_l = 8 * lh + l7;
    const int vrow_l = l7 + 8 * le;

    issue(0); CP_COMMIT();

    for (int kt = 0; kt < 16; kt++) {
        CP_WAIT0();
        __syncthreads();
        if (kt + 1 < 16) issue(kt + 1);
        CP_COMMIT();

        const unsigned kB = sb + (kt & 1) * KV_STG;
        const unsigned vB = kB + 2 * KV_STG;

        float sacc[8][4];
#pragma unroll
        for (int nb = 0; nb < 8; nb++)
#pragma unroll
            for (int r = 0; r < 4; r++) sacc[nb][r] = 0.f;
#pragma unroll
        for (int c = 0; c < 4; c++) {
#pragma unroll
            for (int nbp = 0; nbp < 4; nbp++) {
                unsigned kb[4];
                ldm4(kb, kB + (16 * nbp + krow_l) * 144 + c * 32 + le * 16);
                mma_f16(sacc[2 * nbp], qa[c], kb);
                mma_f16(sacc[2 * nbp + 1], qa[c], kb + 2);
            }
        }

        float rh0a = Bhs[qr0 * LDH + 2 * kt], rh0b = Bhs[qr0 * LDH + 2 * kt + 1];
        float rh1a = Bhs[qr1 * LDH + 2 * kt], rh1b = Bhs[qr1 * LDH + 2 * kt + 1];
        float mn0 = m0, mn1 = m1;
#pragma unroll
        for (int nb = 0; nb < 8; nb++) {
            float bh0 = nb < 4 ? rh0a : rh0b;
            float bh1 = nb < 4 ? rh1a : rh1b;
            int mi = nb & 3;
            sacc[nb][0] = fmaf(sc, sacc[nb][0], bh0 + rw0[2 * mi]);
            sacc[nb][1] = fmaf(sc, sacc[nb][1], bh0 + rw0[2 * mi + 1]);
            sacc[nb][2] = fmaf(sc, sacc[nb][2], bh1 + rw1[2 * mi]);
            sacc[nb][3] = fmaf(sc, sacc[nb][3], bh1 + rw1[2 * mi + 1]);
            mn0 = fmaxf(mn0, fmaxf(sacc[nb][0], sacc[nb][1]));
            mn1 = fmaxf(mn1, fmaxf(sacc[nb][2], sacc[nb][3]));
        }
        mn0 = fmaxf(mn0, __shfl_xor_sync(0xffffffffu, mn0, 1));
        mn0 = fmaxf(mn0, __shfl_xor_sync(0xffffffffu, mn0, 2));
        mn1 = fmaxf(mn1, __shfl_xor_sync(0xffffffffu, mn1, 1));
        mn1 = fmaxf(mn1, __shfl_xor_sync(0xffffffffu, mn1, 2));
        float cr0 = ex2(m0 - mn0), cr1 = ex2(m1 - mn1);
        m0 = mn0; m1 = mn1;
        float s0 = 0.f, s1 = 0.f;
        unsigned ph[8][2];
#pragma unroll
        for (int nb = 0; nb < 8; nb++) {
            float p0 = ex2(sacc[nb][0] - mn0);
            float p1 = ex2(sacc[nb][1] - mn0);
            float p2 = ex2(sacc[nb][2] - mn1);
            float p3 = ex2(sacc[nb][3] - mn1);
            s0 += p0 + p1; s1 += p2 + p3;
            ph[nb][0] = f2h2(p0, p1);
            ph[nb][1] = f2h2(p2, p3);
        }
        s0 += __shfl_xor_sync(0xffffffffu, s0, 1);
        s0 += __shfl_xor_sync(0xffffffffu, s0, 2);
        s1 += __shfl_xor_sync(0xffffffffu, s1, 1);
        s1 += __shfl_xor_sync(0xffffffffu, s1, 2);
        l0 = l0 * cr0 + s0;
        l1 = l1 * cr1 + s1;
#pragma unroll
        for (int nb = 0; nb < 8; nb++) {
            oacc[nb][0] *= cr0; oacc[nb][1] *= cr0;
            oacc[nb][2] *= cr1; oacc[nb][3] *= cr1;
        }

#pragma unroll
        for (int c = 0; c < 4; c++) {
            unsigned pa[4] = {ph[2 * c][0], ph[2 * c][1], ph[2 * c + 1][0], ph[2 * c + 1][1]};
#pragma unroll
            for (int nbp = 0; nbp < 4; nbp++) {
                unsigned vb[4];
                ldm4t(vb, vB + (16 * c + vrow_l) * 144 + nbp * 32 + lh * 16);
                mma_f16(oacc[2 * nbp], pa, vb);
                mma_f16(oacc[2 * nbp + 1], pa, vb + 2);
            }
        }
    }

    float inv0 = 1.f / l0, inv1 = 1.f / l1;
    __half* op0 = &g_attnh[(size_t)(b * SEQ + qbase + qr0) * CH + head * HD + 2 * t4];
    __half* op1 = &g_attnh[(size_t)(b * SEQ + qbase + qr1) * CH + head * HD + 2 * t4];
#pragma unroll
    for (int nb = 0; nb < 8; nb++) {
        *(unsigned*)&op0[8 * nb] = f2h2(oacc[nb][0] * inv0, oacc[nb][1] * inv0);
        *(unsigned*)&op1[8 * nb] = f2h2(oacc[nb][2] * inv1, oacc[nb][3] * inv1);
    }
}

// ============================================================
extern "C" void kernel_launch(void* const* d_in, const int* in_sizes, int n_in,
                              void* d_out, int out_size) {
    const float* x     = (const float*)d_in[0];
    const float* Wqkv  = (const float*)d_in[1];
    const float* Wproj = (const float*)d_in[2];
    const float* bproj = (const float*)d_in[3];
    const float* rph   = (const float*)d_in[4];
    const float* rpw   = (const float*)d_in[5];
    float* out = (float*)d_out;

    __half* qkvh;  cudaGetSymbolAddress((void**)&qkvh,  g_qkvh);
    __half* attnh; cudaGetSymbolAddress((void**)&attnh, g_attnh);
    __half* xh;    cudaGetSymbolAddress((void**)&xh,    g_xh);
    __half* wqh;   cudaGetSymbolAddress((void**)&wqh,   g_wqkvh);
    __half* wph;   cudaGetSymbolAddress((void**)&wph,   g_wprojh);

    cudaFuncSetAttribute(gemm_h<1>, cudaFuncAttributeMaxDynamicSharedMemorySize, GEMM_SMEM);
    cudaFuncSetAttribute(gemm_h<2>, cudaFuncAttributeMaxDynamicSharedMemorySize, GEMM_SMEM);
    cudaFuncSetAttribute(attn_mma, cudaFuncAttributeMaxDynamicSharedMemorySize, ATTN_SMEM);

    // 0) f32 -> f16 conversions
    {
        int n2 = NB * SEQ * CH / 2;
        f2h_kernel<<<(n2 + 255) / 256, 256>>>(x, xh, n2);
        n2 = CH * 3 * CH / 2;
        f2h_kernel<<<(n2 + 255) / 256, 256>>>(Wqkv, wqh, n2);
        n2 = CH * CH / 2;
        f2h_kernel<<<(n2 + 255) / 256, 256>>>(Wproj, wph, n2);
    }

    // 1) QKV projection: fp16 out
    gemm_h<2><<<dim3(QKVLD / 128, (NB * SEQ) / 128), 256, GEMM_SMEM>>>(
        xh, wqh, nullptr, nullptr, qkvh, NB * SEQ, QKVLD, CH);

    // 2) decomposed relative position bias (tensor cores)
    relpos_mma<<<dim3(2, BHD), 256>>>(rph, rpw);

    // 3) attention (fp16 mma, register-resident P, single-sync loop)
    attn_mma<<<dim3(SEQ / BQ, BHD), 256, ATTN_SMEM>>>();

    // 4) out projection + bias -> f32 output
    gemm_h<1><<<dim3(CH / 128, (NB * SEQ) / 128), 256, GEMM_SMEM>>>(
        attnh, wph, bproj, out, nullptr, NB * SEQ, CH, CH);
}